// round 13
// baseline (speedup 1.0000x reference)
#include <cuda_runtime.h>

#define FID 65536
#define BATCH 2048
#define ROW_V4 (FID / 4)        // 16384 float4 per row
#define NBLK (BATCH / 2)        // 2 rows per block -> 1024 blocks (single wave)

// fp64 loss accumulator stored as raw bits so we can atomicExch-drain it.
// zero-init (0ull == bits of 0.0); drained to 0 each replay -> replay-safe.
__device__ unsigned long long g_loss_bits;
__device__ unsigned int       g_done_count;   // zero-init; atomicInc wraps -> replay-safe

__global__ __launch_bounds__(256, 8) void fused_lr_final_kernel(
    const float* __restrict__ gate,
    const float* __restrict__ bias,
    const float* __restrict__ gbias,
    const float* __restrict__ label,
    float* __restrict__ logits,
    float* __restrict__ pred,
    float* __restrict__ loss)
{
    const int r0 = blockIdx.x * 2;       // rows r0, r0+1
    const float4* __restrict__ g0 = reinterpret_cast<const float4*>(gate + (size_t)r0 * FID);
    const float4* __restrict__ g1 = g0 + ROW_V4;
    const float4* __restrict__ b  = reinterpret_cast<const float4*>(bias);

    // Best-measured loop (R7): plain loads (all cache hints regress on this
    // workload: R2/R6/R9), 6 loads front-batched per iter for MLP, 16 FMAs,
    // 32-reg budget -> 8 blocks/SM, grid fits one resident wave.
    float acc0 = 0.0f, acc1 = 0.0f;
    for (int i = threadIdx.x; i < ROW_V4; i += 2 * 256) {
        const int j = i + 256;
        float4 va0 = g0[i];
        float4 vb0 = g1[i];
        float4 va1 = g0[j];
        float4 vb1 = g1[j];
        float4 ba  = b[i];
        float4 bb  = b[j];
        acc0 = fmaf(va0.x, ba.x, acc0);
        acc0 = fmaf(va0.y, ba.y, acc0);
        acc0 = fmaf(va0.z, ba.z, acc0);
        acc0 = fmaf(va0.w, ba.w, acc0);
        acc1 = fmaf(vb0.x, ba.x, acc1);
        acc1 = fmaf(vb0.y, ba.y, acc1);
        acc1 = fmaf(vb0.z, ba.z, acc1);
        acc1 = fmaf(vb0.w, ba.w, acc1);
        acc0 = fmaf(va1.x, bb.x, acc0);
        acc0 = fmaf(va1.y, bb.y, acc0);
        acc0 = fmaf(va1.z, bb.z, acc0);
        acc0 = fmaf(va1.w, bb.w, acc0);
        acc1 = fmaf(vb1.x, bb.x, acc1);
        acc1 = fmaf(vb1.y, bb.y, acc1);
        acc1 = fmaf(vb1.z, bb.z, acc1);
        acc1 = fmaf(vb1.w, bb.w, acc1);
    }

    // block reduce both accumulators (fixed order -> deterministic logits)
    #pragma unroll
    for (int off = 16; off > 0; off >>= 1) {
        acc0 += __shfl_down_sync(0xFFFFFFFFu, acc0, off);
        acc1 += __shfl_down_sync(0xFFFFFFFFu, acc1, off);
    }

    __shared__ float smem0[8], smem1[8];
    const int lane = threadIdx.x & 31;
    const int wid  = threadIdx.x >> 5;
    if (lane == 0) { smem0[wid] = acc0; smem1[wid] = acc1; }
    __syncthreads();

    if (threadIdx.x == 0) {
        float gb = gbias[0];
        float z0 = smem0[0] + smem0[1] + smem0[2] + smem0[3]
                 + smem0[4] + smem0[5] + smem0[6] + smem0[7] + gb;
        float z1 = smem1[0] + smem1[1] + smem1[2] + smem1[3]
                 + smem1[4] + smem1[5] + smem1[6] + smem1[7] + gb;

        logits[r0]     = z0;
        logits[r0 + 1] = z1;
        pred[r0]       = 1.0f / (1.0f + __expf(-z0));
        pred[r0 + 1]   = 1.0f / (1.0f + __expf(-z1));

        float y0 = label[r0], y1 = label[r0 + 1];
        float l0 = fmaxf(z0, 0.0f) - z0 * y0 + log1pf(expf(-fabsf(z0)));
        float l1 = fmaxf(z1, 0.0f) - z1 * y1 + log1pf(expf(-fabsf(z1)));

        // fp64 accumulation: order-dependence ~1e-16, invisible after float rounding
        atomicAdd(reinterpret_cast<double*>(&g_loss_bits), (double)l0 + (double)l1);

        __threadfence();                                   // release our add
        unsigned int ticket = atomicInc(&g_done_count, NBLK - 1);  // wraps -> replay-safe
        if (ticket == NBLK - 1) {
            __threadfence();                               // acquire all adds
            // drain-and-reset in one op: total out, 0 bits (=0.0) left for next replay
            unsigned long long bits = atomicExch(&g_loss_bits, 0ull);
            loss[0] = (float)__longlong_as_double(bits);
        }
    }
}

extern "C" void kernel_launch(void* const* d_in, const int* in_sizes, int n_in,
                              void* d_out, int out_size)
{
    // Inputs: 0 gate [2048,65536] f32, 1 sparse_bias [65536] f32,
    //         2 global_bias [1] f32, 3 label [2048] f32
    const float* gate  = (const float*)d_in[0];
    const float* bias  = (const float*)d_in[1];
    const float* gbias = (const float*)d_in[2];
    const float* label = (const float*)d_in[3];

    // Output: logits[2048], pred[2048], loss[1]
    float* out    = (float*)d_out;
    float* logits = out;
    float* pred   = out + BATCH;
    float* loss   = out + 2 * BATCH;

    fused_lr_final_kernel<<<NBLK, 256>>>(gate, bias, gbias, label, logits, pred, loss);
}

// round 14
// speedup vs baseline: 1.0004x; 1.0004x over previous
#include <cuda_runtime.h>

#define FID 65536
#define BATCH 2048
#define ROW_V4 (FID / 4)        // 16384 float4 per row
#define NBLK BATCH              // 1 row per block -> 2048 blocks, still ONE wave
                                // (16 blocks/SM x 128 thr = 2048 thr/SM; 16*148=2368 >= 2048)

// fp64 loss accumulator stored as raw bits so we can atomicExch-drain it.
// zero-init (0ull == bits of 0.0); drained to 0 each replay -> replay-safe.
__device__ unsigned long long g_loss_bits;
__device__ unsigned int       g_done_count;   // zero-init; atomicInc wraps -> replay-safe

__global__ __launch_bounds__(128, 16) void fused_lr_fine_kernel(
    const float* __restrict__ gate,
    const float* __restrict__ bias,
    const float* __restrict__ gbias,
    const float* __restrict__ label,
    float* __restrict__ logits,
    float* __restrict__ pred,
    float* __restrict__ loss)
{
    const int row = blockIdx.x;
    const float4* __restrict__ g = reinterpret_cast<const float4*>(gate + (size_t)row * FID);
    const float4* __restrict__ b = reinterpret_cast<const float4*>(bias);

    // Plain loads (cache hints regress: R2/R6/R9). 4 loads front-batched
    // per iteration, 8 FMAs consume. 128 iters/thread.
    float acc0 = 0.0f, acc1 = 0.0f;
    for (int i = threadIdx.x; i < ROW_V4; i += 2 * 128) {
        const int j = i + 128;
        float4 gv0 = g[i];
        float4 gv1 = g[j];
        float4 bv0 = b[i];
        float4 bv1 = b[j];
        acc0 = fmaf(gv0.x, bv0.x, acc0);
        acc0 = fmaf(gv0.y, bv0.y, acc0);
        acc0 = fmaf(gv0.z, bv0.z, acc0);
        acc0 = fmaf(gv0.w, bv0.w, acc0);
        acc1 = fmaf(gv1.x, bv1.x, acc1);
        acc1 = fmaf(gv1.y, bv1.y, acc1);
        acc1 = fmaf(gv1.z, bv1.z, acc1);
        acc1 = fmaf(gv1.w, bv1.w, acc1);
    }
    float acc = acc0 + acc1;

    // block reduce (fixed order -> deterministic logits)
    #pragma unroll
    for (int off = 16; off > 0; off >>= 1)
        acc += __shfl_down_sync(0xFFFFFFFFu, acc, off);

    __shared__ float smem[4];
    const int lane = threadIdx.x & 31;
    const int wid  = threadIdx.x >> 5;
    if (lane == 0) smem[wid] = acc;
    __syncthreads();

    if (threadIdx.x == 0) {
        float z = smem[0] + smem[1] + smem[2] + smem[3] + gbias[0];

        logits[row] = z;
        pred[row]   = 1.0f / (1.0f + __expf(-z));

        float y = label[row];
        float l = fmaxf(z, 0.0f) - z * y + log1pf(expf(-fabsf(z)));

        // fp64 accumulation: order-dependence ~1e-16, invisible after float rounding
        atomicAdd(reinterpret_cast<double*>(&g_loss_bits), (double)l);

        __threadfence();                                   // release our add
        unsigned int ticket = atomicInc(&g_done_count, NBLK - 1);  // wraps -> replay-safe
        if (ticket == NBLK - 1) {
            __threadfence();                               // acquire all adds
            // drain-and-reset in one op: total out, 0 bits (=0.0) left for next replay
            unsigned long long bits = atomicExch(&g_loss_bits, 0ull);
            loss[0] = (float)__longlong_as_double(bits);
        }
    }
}

extern "C" void kernel_launch(void* const* d_in, const int* in_sizes, int n_in,
                              void* d_out, int out_size)
{
    // Inputs: 0 gate [2048,65536] f32, 1 sparse_bias [65536] f32,
    //         2 global_bias [1] f32, 3 label [2048] f32
    const float* gate  = (const float*)d_in[0];
    const float* bias  = (const float*)d_in[1];
    const float* gbias = (const float*)d_in[2];
    const float* label = (const float*)d_in[3];

    // Output: logits[2048], pred[2048], loss[1]
    float* out    = (float*)d_out;
    float* logits = out;
    float* pred   = out + BATCH;
    float* loss   = out + 2 * BATCH;

    fused_lr_fine_kernel<<<NBLK, 128>>>(gate, bias, gbias, label, logits, pred, loss);
}

// round 15
// speedup vs baseline: 1.0118x; 1.0114x over previous
#include <cuda_runtime.h>

#define FID 65536
#define BATCH 2048
#define ROW_V4 (FID / 4)        // 16384 float4 per row
#define NBLK (BATCH / 2)        // 2 rows per block -> 1024 blocks (single wave)

__device__ float        g_row_loss[BATCH];
__device__ unsigned int g_done_count;      // zero-init; atomicInc wraps -> replay-safe

__global__ __launch_bounds__(256, 8) void fused_lr2u_kernel(
    const float* __restrict__ gate,
    const float* __restrict__ bias,
    const float* __restrict__ gbias,
    const float* __restrict__ label,
    float* __restrict__ logits,
    float* __restrict__ pred,
    float* __restrict__ loss)
{
    const int r0 = blockIdx.x * 2;       // rows r0, r0+1
    const float4* __restrict__ g0 = reinterpret_cast<const float4*>(gate + (size_t)r0 * FID);
    const float4* __restrict__ g1 = g0 + ROW_V4;
    const float4* __restrict__ b  = reinterpret_cast<const float4*>(bias);

    // Champion loop (R7, 82.0us): plain loads (cache hints regress on this
    // workload: R2/R6/R9), 6 loads front-batched per iteration for MLP,
    // 16 FMAs consume, 32-reg budget -> 8 blocks/SM, one resident wave.
    float acc0 = 0.0f, acc1 = 0.0f;
    for (int i = threadIdx.x; i < ROW_V4; i += 2 * 256) {
        const int j = i + 256;
        float4 va0 = g0[i];
        float4 vb0 = g1[i];
        float4 va1 = g0[j];
        float4 vb1 = g1[j];
        float4 ba  = b[i];
        float4 bb  = b[j];
        acc0 = fmaf(va0.x, ba.x, acc0);
        acc0 = fmaf(va0.y, ba.y, acc0);
        acc0 = fmaf(va0.z, ba.z, acc0);
        acc0 = fmaf(va0.w, ba.w, acc0);
        acc1 = fmaf(vb0.x, ba.x, acc1);
        acc1 = fmaf(vb0.y, ba.y, acc1);
        acc1 = fmaf(vb0.z, ba.z, acc1);
        acc1 = fmaf(vb0.w, ba.w, acc1);
        acc0 = fmaf(va1.x, bb.x, acc0);
        acc0 = fmaf(va1.y, bb.y, acc0);
        acc0 = fmaf(va1.z, bb.z, acc0);
        acc0 = fmaf(va1.w, bb.w, acc0);
        acc1 = fmaf(vb1.x, bb.x, acc1);
        acc1 = fmaf(vb1.y, bb.y, acc1);
        acc1 = fmaf(vb1.z, bb.z, acc1);
        acc1 = fmaf(vb1.w, bb.w, acc1);
    }

    // block reduce both accumulators (fixed order -> deterministic)
    #pragma unroll
    for (int off = 16; off > 0; off >>= 1) {
        acc0 += __shfl_down_sync(0xFFFFFFFFu, acc0, off);
        acc1 += __shfl_down_sync(0xFFFFFFFFu, acc1, off);
    }

    __shared__ float smem0[8], smem1[8];
    const int lane = threadIdx.x & 31;
    const int wid  = threadIdx.x >> 5;
    if (lane == 0) { smem0[wid] = acc0; smem1[wid] = acc1; }
    __syncthreads();

    __shared__ bool s_is_last;
    if (threadIdx.x == 0) {
        float gb = gbias[0];
        float z0 = smem0[0] + smem0[1] + smem0[2] + smem0[3]
                 + smem0[4] + smem0[5] + smem0[6] + smem0[7] + gb;
        float z1 = smem1[0] + smem1[1] + smem1[2] + smem1[3]
                 + smem1[4] + smem1[5] + smem1[6] + smem1[7] + gb;

        logits[r0]     = z0;
        logits[r0 + 1] = z1;
        pred[r0]       = 1.0f / (1.0f + __expf(-z0));
        pred[r0 + 1]   = 1.0f / (1.0f + __expf(-z1));
        float y0 = label[r0], y1 = label[r0 + 1];
        g_row_loss[r0]     = fmaxf(z0, 0.0f) - z0 * y0 + log1pf(expf(-fabsf(z0)));
        g_row_loss[r0 + 1] = fmaxf(z1, 0.0f) - z1 * y1 + log1pf(expf(-fabsf(z1)));

        __threadfence();
        unsigned int ticket = atomicInc(&g_done_count, NBLK - 1);  // wraps -> replay-safe
        s_is_last = (ticket == NBLK - 1);
    }
    __syncthreads();

    if (s_is_last) {
        // deterministic fixed-order reduction of 2048 per-row losses
        float lsum = 0.0f;
        #pragma unroll
        for (int k = 0; k < BATCH / 256; k++)
            lsum += g_row_loss[threadIdx.x + k * 256];

        #pragma unroll
        for (int off = 16; off > 0; off >>= 1)
            lsum += __shfl_down_sync(0xFFFFFFFFu, lsum, off);

        __shared__ float smem2[8];
        if (lane == 0) smem2[wid] = lsum;
        __syncthreads();
        if (threadIdx.x == 0) {
            loss[0] = smem2[0] + smem2[1] + smem2[2] + smem2[3]
                    + smem2[4] + smem2[5] + smem2[6] + smem2[7];
        }
    }
}

extern "C" void kernel_launch(void* const* d_in, const int* in_sizes, int n_in,
                              void* d_out, int out_size)
{
    // Inputs: 0 gate [2048,65536] f32, 1 sparse_bias [65536] f32,
    //         2 global_bias [1] f32, 3 label [2048] f32
    const float* gate  = (const float*)d_in[0];
    const float* bias  = (const float*)d_in[1];
    const float* gbias = (const float*)d_in[2];
    const float* label = (const float*)d_in[3];

    // Output: logits[2048], pred[2048], loss[1]
    float* out    = (float*)d_out;
    float* logits = out;
    float* pred   = out + BATCH;
    float* loss   = out + 2 * BATCH;

    fused_lr2u_kernel<<<NBLK, 256>>>(gate, bias, gbias, label, logits, pred, loss);
}

// round 16
// speedup vs baseline: 1.0210x; 1.0091x over previous
#include <cuda_runtime.h>

#define FID 65536
#define BATCH 2048
#define ROW_V4 (FID / 4)        // 16384 float4 per row
#define NBLK (BATCH / 2)        // 2 rows per block -> 1024 blocks (single wave)

__device__ float        g_row_loss[BATCH];
__device__ unsigned int g_done_count;      // zero-init; atomicInc wraps -> replay-safe

__global__ __launch_bounds__(256, 8) void fused_lr2u_kernel(
    const float* __restrict__ gate,
    const float* __restrict__ bias,
    const float* __restrict__ gbias,
    const float* __restrict__ label,
    float* __restrict__ logits,
    float* __restrict__ pred,
    float* __restrict__ loss)
{
    const int r0 = blockIdx.x * 2;       // rows r0, r0+1
    const float4* __restrict__ g0 = reinterpret_cast<const float4*>(gate + (size_t)r0 * FID);
    const float4* __restrict__ g1 = g0 + ROW_V4;
    const float4* __restrict__ b  = reinterpret_cast<const float4*>(bias);

    // Champion loop (best measured 81.5us): plain loads (cache hints regress
    // on this workload: R2/R6/R9), 6 loads front-batched per iteration for
    // MLP, 16 FMAs consume, 32-reg budget -> 8 blocks/SM, one resident wave.
    float acc0 = 0.0f, acc1 = 0.0f;
    for (int i = threadIdx.x; i < ROW_V4; i += 2 * 256) {
        const int j = i + 256;
        float4 va0 = g0[i];
        float4 vb0 = g1[i];
        float4 va1 = g0[j];
        float4 vb1 = g1[j];
        float4 ba  = b[i];
        float4 bb  = b[j];
        acc0 = fmaf(va0.x, ba.x, acc0);
        acc0 = fmaf(va0.y, ba.y, acc0);
        acc0 = fmaf(va0.z, ba.z, acc0);
        acc0 = fmaf(va0.w, ba.w, acc0);
        acc1 = fmaf(vb0.x, ba.x, acc1);
        acc1 = fmaf(vb0.y, ba.y, acc1);
        acc1 = fmaf(vb0.z, ba.z, acc1);
        acc1 = fmaf(vb0.w, ba.w, acc1);
        acc0 = fmaf(va1.x, bb.x, acc0);
        acc0 = fmaf(va1.y, bb.y, acc0);
        acc0 = fmaf(va1.z, bb.z, acc0);
        acc0 = fmaf(va1.w, bb.w, acc0);
        acc1 = fmaf(vb1.x, bb.x, acc1);
        acc1 = fmaf(vb1.y, bb.y, acc1);
        acc1 = fmaf(vb1.z, bb.z, acc1);
        acc1 = fmaf(vb1.w, bb.w, acc1);
    }

    // block reduce both accumulators (fixed order -> deterministic)
    #pragma unroll
    for (int off = 16; off > 0; off >>= 1) {
        acc0 += __shfl_down_sync(0xFFFFFFFFu, acc0, off);
        acc1 += __shfl_down_sync(0xFFFFFFFFu, acc1, off);
    }

    __shared__ float smem0[8], smem1[8];
    const int lane = threadIdx.x & 31;
    const int wid  = threadIdx.x >> 5;
    if (lane == 0) { smem0[wid] = acc0; smem1[wid] = acc1; }
    __syncthreads();

    __shared__ bool s_is_last;
    if (threadIdx.x == 0) {
        float gb = gbias[0];
        float z0 = smem0[0] + smem0[1] + smem0[2] + smem0[3]
                 + smem0[4] + smem0[5] + smem0[6] + smem0[7] + gb;
        float z1 = smem1[0] + smem1[1] + smem1[2] + smem1[3]
                 + smem1[4] + smem1[5] + smem1[6] + smem1[7] + gb;

        logits[r0]     = z0;
        logits[r0 + 1] = z1;
        pred[r0]       = 1.0f / (1.0f + __expf(-z0));
        pred[r0 + 1]   = 1.0f / (1.0f + __expf(-z1));
        float y0 = label[r0], y1 = label[r0 + 1];
        g_row_loss[r0]     = fmaxf(z0, 0.0f) - z0 * y0 + log1pf(expf(-fabsf(z0)));
        g_row_loss[r0 + 1] = fmaxf(z1, 0.0f) - z1 * y1 + log1pf(expf(-fabsf(z1)));

        __threadfence();
        unsigned int ticket = atomicInc(&g_done_count, NBLK - 1);  // wraps -> replay-safe
        s_is_last = (ticket == NBLK - 1);
    }
    __syncthreads();

    if (s_is_last) {
        // deterministic fixed-order reduction of 2048 per-row losses
        float lsum = 0.0f;
        #pragma unroll
        for (int k = 0; k < BATCH / 256; k++)
            lsum += g_row_loss[threadIdx.x + k * 256];

        #pragma unroll
        for (int off = 16; off > 0; off >>= 1)
            lsum += __shfl_down_sync(0xFFFFFFFFu, lsum, off);

        __shared__ float smem2[8];
        if (lane == 0) smem2[wid] = lsum;
        __syncthreads();
        if (threadIdx.x == 0) {
            loss[0] = smem2[0] + smem2[1] + smem2[2] + smem2[3]
                    + smem2[4] + smem2[5] + smem2[6] + smem2[7];
        }
    }
}

extern "C" void kernel_launch(void* const* d_in, const int* in_sizes, int n_in,
                              void* d_out, int out_size)
{
    // Inputs: 0 gate [2048,65536] f32, 1 sparse_bias [65536] f32,
    //         2 global_bias [1] f32, 3 label [2048] f32
    const float* gate  = (const float*)d_in[0];
    const float* bias  = (const float*)d_in[1];
    const float* gbias = (const float*)d_in[2];
    const float* label = (const float*)d_in[3];

    // Output: logits[2048], pred[2048], loss[1]
    float* out    = (float*)d_out;
    float* logits = out;
    float* pred   = out + BATCH;
    float* loss   = out + 2 * BATCH;

    fused_lr2u_kernel<<<NBLK, 256>>>(gate, bias, gbias, label, logits, pred, loss);
}